// round 11
// baseline (speedup 1.0000x reference)
#include <cuda_runtime.h>
#include <cuda_bf16.h>
#include <cstdint>

#define S_LEN    2048
#define L        50
#define TILE     122
#define RROWS    128
#define NTHREADS 1024
#define NTILES   ((S_LEN + TILE - 1) / TILE)

#define AHW 68    // uint32 words per A row (136 bf16; 68 % 32 == 4 -> conflict-free)
#define DST 70
#define UST 57

// smem byte offsets from 1024-aligned base
#define OFF_AHI 0u
#define OFF_ALO 34816u
#define OFF_BF  69632u      // B frags: 7 nt x 8 ks x 32 lanes x uint4
#define OFF_D   98304u
#define OFF_U   134144u
#define OFF_MSK 163328u
#define OFF_TS  163840u
#define OFF_TE  164096u
#define SMEM_BYTES (164352 + 1024)

__device__ __forceinline__ uint32_t bfpack(float lo, float hi) {
    uint32_t r;
    asm("cvt.rn.bf16x2.f32 %0, %1, %2;" : "=r"(r) : "f"(hi), "f"(lo));
    return r;
}
__device__ __forceinline__ float bfhi(float v) {
    return __bfloat162float(__float2bfloat16_rn(v));
}
__device__ __forceinline__ void mma16(float* d, uint32_t a0, uint32_t a1,
                                      uint32_t a2, uint32_t a3,
                                      uint32_t b0, uint32_t b1) {
    asm volatile(
        "mma.sync.aligned.m16n8k16.row.col.f32.bf16.bf16.f32 "
        "{%0,%1,%2,%3}, {%4,%5,%6,%7}, {%8,%9}, {%0,%1,%2,%3};"
        : "+f"(d[0]), "+f"(d[1]), "+f"(d[2]), "+f"(d[3])
        : "r"(a0), "r"(a1), "r"(a2), "r"(a3), "r"(b0), "r"(b1));
}

__global__ __launch_bounds__(NTHREADS, 1) void mfvi_kernel(
    const float* __restrict__ unary,
    const float* __restrict__ mask,
    const float* __restrict__ Tg,
    const float* __restrict__ tstart,
    const float* __restrict__ tend,
    float* __restrict__ out)
{
    extern __shared__ char dsm_raw[];
    char* smp = (char*)(((uintptr_t)dsm_raw + 1023) & ~(uintptr_t)1023);
    uint32_t* AhiU = (uint32_t*)(smp + OFF_AHI);
    uint32_t* AloU = (uint32_t*)(smp + OFF_ALO);
    uint4*    Bf   = (uint4*)   (smp + OFF_BF);
    float*    Dsm  = (float*)   (smp + OFF_D);
    float*    Usm  = (float*)   (smp + OFF_U);
    float*    Msk  = (float*)   (smp + OFF_MSK);
    float*    Tss  = (float*)   (smp + OFF_TS);
    float*    Tes  = (float*)   (smp + OFF_TE);

    const int n    = blockIdx.y;
    const int p0   = blockIdx.x * TILE;
    const int base = p0 - 3;
    const int tid  = threadIdx.x;

    // ---- prologue: zero A hi+lo (pads/halo rows must stay 0) ----
    {
        float4 z = make_float4(0.f, 0.f, 0.f, 0.f);
        for (int i = tid; i < (int)(2 * 34816 / 16); i += NTHREADS)
            ((float4*)(smp + OFF_AHI))[i] = z;
    }
    // ---- B fragments, bf16 hi/lo, exact m16n8k16 col-major fragment order ----
    // B'[bn][k]: k<50 -> T[k][bn] ; 64<=k<114 -> T[bn][k-64] ; else 0
    for (int idx = tid; idx < 7 * 8 * 32; idx += NTHREADS) {
        int lane = idx & 31, rem = idx >> 5;
        int ks = rem & 7, nt = rem >> 3;
        int gI = lane >> 2, tI = lane & 3;
        int bn = nt * 8 + gI;
        int k0 = 16 * ks + 2 * tI;
        float v[4];
        #pragma unroll
        for (int h = 0; h < 4; h++) {
            int k = k0 + (h >> 1) * 8 + (h & 1);
            float val = 0.f;
            if (bn < L) {
                if (k < L)                        val = Tg[k * L + bn];
                else if (k >= 64 && k < 64 + L)   val = Tg[bn * L + (k - 64)];
            }
            v[h] = val;
        }
        uint4 o;
        o.x = bfpack(v[0], v[1]);
        o.y = bfpack(v[2], v[3]);
        o.z = bfpack(v[0] - bfhi(v[0]), v[1] - bfhi(v[1]));
        o.w = bfpack(v[2] - bfhi(v[2]), v[3] - bfhi(v[3]));
        Bf[idx] = o;
    }
    if (tid < 128) {
        int g = base + tid;
        Msk[tid] = (g >= 0 && g < S_LEN) ? mask[(size_t)n * S_LEN + g] : 0.f;
    }
    if (tid < 64) {
        Tss[tid] = (tid < L) ? tstart[tid] : 0.f;
        Tes[tid] = (tid < L) ? tend[tid]   : 0.f;
    }
    __syncthreads();
    for (int idx = tid; idx < 128 * UST; idx += NTHREADS) {
        int rr = idx / UST, c = idx - rr * UST;
        int gg = base + rr;
        float v = 0.f;
        if (c < L && gg >= 0 && gg < S_LEN)
            v = unary[((size_t)n * S_LEN + gg) * L + c] * Msk[rr];
        Usm[idx] = v;
    }
    __syncthreads();

    #pragma unroll 1
    for (int it = 0; it <= 3; it++) {
        // ==== build: 8 threads/row, thread = 8-label strip [8*sub, 8*sub+8) ====
        {
            const int r     = tid >> 3;
            const int sub   = tid & 7;
            const int cbase = 8 * sub;
            const int cnt   = (sub < 6) ? 8 : (sub == 6 ? 2 : 0);
            const int g     = base + r;
            const bool act  = (g >= 0) && (g < S_LEN) && (r >= it) && (r < RROWS - it);

            float q[8];
            if (it == 0) {
                #pragma unroll
                for (int i = 0; i < 8; i++)
                    if (i < cnt) q[i] = Usm[r * UST + cbase + i];
            } else {
                const float  m   = Msk[r];
                const float* bnd = (g == 0) ? Tss : Tes;  // pos0: tstart; >=1: tend
                #pragma unroll
                for (int i = 0; i < 8; i++)
                    if (i < cnt)
                        q[i] = (Usm[r * UST + cbase + i] + Dsm[r * DST + cbase + i]
                                + bnd[cbase + i]) * m;
            }
            if (it == 3) {
                if (act) {
                    float* st = (float*)(smp + OFF_AHI);   // reuse A as staging
                    #pragma unroll
                    for (int i = 0; i < 8; i++)
                        if (i < cnt) st[(r - 3) * 50 + cbase + i] = q[i];
                }
            } else {
                float mx = -3.4e38f;
                #pragma unroll
                for (int i = 0; i < 8; i++) if (i < cnt) mx = fmaxf(mx, q[i]);
                #pragma unroll
                for (int o = 1; o < 8; o <<= 1)
                    mx = fmaxf(mx, __shfl_xor_sync(0xffffffffu, mx, o));
                float s = 0.f;
                #pragma unroll
                for (int i = 0; i < 8; i++)
                    if (i < cnt) { q[i] = __expf(q[i] - mx); s += q[i]; }
                #pragma unroll
                for (int o = 1; o < 8; o <<= 1)
                    s += __shfl_xor_sync(0xffffffffu, s, o);
                float inv = __fdividef(1.f, s);
                if (act) {
                    const int pb = 4 * sub;
                    const int np = cnt >> 1;
                    // p[r] -> left-half of row r+1, right-half (+32) of row r-1
                    #pragma unroll
                    for (int pi = 0; pi < 4; pi++) {
                        if (pi < np) {
                            float pa = q[2 * pi] * inv;
                            float pz = q[2 * pi + 1] * inv;
                            uint32_t ph = bfpack(pa, pz);
                            uint32_t pl = bfpack(pa - bfhi(pa), pz - bfhi(pz));
                            if (r + 1 < RROWS) {
                                AhiU[(r + 1) * AHW + pb + pi] = ph;
                                AloU[(r + 1) * AHW + pb + pi] = pl;
                            }
                            if (r - 1 >= 0) {
                                AhiU[(r - 1) * AHW + 32 + pb + pi] = ph;
                                AloU[(r - 1) * AHW + 32 + pb + pi] = pl;
                            }
                        }
                    }
                }
            }
        }
        __syncthreads();
        if (it == 3) break;

        // ==== MMA: 32 warps = 8 row-blocks x 4 col-groups, bf16 3-split ====
        {
            const int w   = tid >> 5;
            const int l   = tid & 31;
            const int gID = l >> 2;
            const int tID = l & 3;
            const int R0  = 16 * (w >> 2);
            const int cg  = w & 3;
            const int nt0 = 2 * cg;
            const int ntc = (cg < 3) ? 2 : 1;

            float acc[2][4];
            #pragma unroll
            for (int j = 0; j < 2; j++)
                #pragma unroll
                for (int k = 0; k < 4; k++) acc[j][k] = 0.f;

            const uint32_t* Ah = AhiU + (R0 + gID) * AHW + tID;
            const uint32_t* Al = AloU + (R0 + gID) * AHW + tID;
            #pragma unroll
            for (int ks = 0; ks < 8; ks++) {
                const int kb = 8 * ks;
                uint32_t a0h = Ah[kb],           a2h = Ah[kb + 4];
                uint32_t a1h = Ah[8 * AHW + kb], a3h = Ah[8 * AHW + kb + 4];
                uint32_t a0l = Al[kb],           a2l = Al[kb + 4];
                uint32_t a1l = Al[8 * AHW + kb], a3l = Al[8 * AHW + kb + 4];
                const uint4* bp = Bf + (nt0 * 8 + ks) * 32 + l;
                #pragma unroll
                for (int j = 0; j < 2; j++) {
                    if (j < ntc) {                        // warp-uniform guard
                        uint4 b = bp[j * 8 * 32];
                        mma16(acc[j], a0h, a1h, a2h, a3h, b.x, b.y);
                        mma16(acc[j], a0l, a1l, a2l, a3l, b.x, b.y);
                        mma16(acc[j], a0h, a1h, a2h, a3h, b.z, b.w);
                    }
                }
            }
            #pragma unroll
            for (int j = 0; j < 2; j++) {
                if (j < ntc) {
                    int c0 = (nt0 + j) * 8 + 2 * tID;
                    *(float2*)&Dsm[(R0 + gID) * DST + c0] =
                        make_float2(acc[j][0], acc[j][1]);
                    *(float2*)&Dsm[(R0 + gID + 8) * DST + c0] =
                        make_float2(acc[j][2], acc[j][3]);
                }
            }
        }
        __syncthreads();
    }

    // ---- epilogue: coalesced staging -> global ----
    {
        int rows = min(TILE, S_LEN - p0);
        int nvec = rows * L / 4;
        const float4* s4 = (const float4*)(smp + OFF_AHI);
        float4* o4 = (float4*)(out + ((size_t)n * S_LEN + p0) * L);
        for (int i = tid; i < nvec; i += NTHREADS) o4[i] = s4[i];
    }
}

extern "C" void kernel_launch(void* const* d_in, const int* in_sizes, int n_in,
                              void* d_out, int out_size)
{
    const float* unary = (const float*)d_in[0];
    const float* mask  = (const float*)d_in[1];
    const float* T     = (const float*)d_in[2];
    const float* ts    = (const float*)d_in[3];
    const float* te    = (const float*)d_in[4];
    (void)n_in; (void)out_size;

    cudaFuncSetAttribute(mfvi_kernel,
                         cudaFuncAttributeMaxDynamicSharedMemorySize, SMEM_BYTES);

    int NS = in_sizes[1];
    int N  = NS / S_LEN;
    dim3 grid(NTILES, N);
    mfvi_kernel<<<grid, NTHREADS, SMEM_BYTES>>>(unary, mask, T, ts, te, (float*)d_out);
}

// round 12
// speedup vs baseline: 1.1200x; 1.1200x over previous
#include <cuda_runtime.h>
#include <cuda_bf16.h>
#include <cstdint>

#define S_LEN    2048
#define L        50
#define TILE     58
#define RROWS    64
#define NTHREADS 512
#define NTILES   ((S_LEN + TILE - 1) / TILE)   // 36

#define DST 72    // floats per D row (16B-aligned rows)
#define UST 56    // floats per U row (16B-aligned rows)

// smem byte offsets from 1024-aligned base
#define OFF_AHI 0u          // A hi frags: 4 rb x 8 ks x 32 lanes x uint4 = 16384
#define OFF_ALO 16384u
#define OFF_BF  32768u      // B frags: 7 nt x 8 ks x 32 lanes x uint4 = 28672
#define OFF_D   61440u      // 64 x 72 x 4 = 18432
#define OFF_U   79872u      // 64 x 56 x 4 = 14336
#define OFF_MSK 94208u
#define OFF_TS  94464u
#define OFF_TE  94720u
#define SMEM_BYTES (94976 + 1024)

__device__ __forceinline__ uint32_t bfpack(float lo, float hi) {
    uint32_t r;
    asm("cvt.rn.bf16x2.f32 %0, %1, %2;" : "=r"(r) : "f"(hi), "f"(lo));
    return r;
}
__device__ __forceinline__ float bfhi(float v) {
    return __bfloat162float(__float2bfloat16_rn(v));
}
__device__ __forceinline__ void mma16(float* d, uint32_t a0, uint32_t a1,
                                      uint32_t a2, uint32_t a3,
                                      uint32_t b0, uint32_t b1) {
    asm volatile(
        "mma.sync.aligned.m16n8k16.row.col.f32.bf16.bf16.f32 "
        "{%0,%1,%2,%3}, {%4,%5,%6,%7}, {%8,%9}, {%0,%1,%2,%3};"
        : "+f"(d[0]), "+f"(d[1]), "+f"(d[2]), "+f"(d[3])
        : "r"(a0), "r"(a1), "r"(a2), "r"(a3), "r"(b0), "r"(b1));
}

// word index (uint32 units) of A-fragment word (row, w) in frag-order layout
__device__ __forceinline__ int fragidx(int row, int w) {
    int rb = row >> 4, rr = row & 15;
    int ks = w >> 3, win = w & 7, tI = win & 3;
    int c = ((win >= 4) ? 2 : 0) + ((rr >= 8) ? 1 : 0);
    return (((rb * 8 + ks) * 32) + (rr & 7) * 4 + tI) * 4 + c;
}

__global__ __launch_bounds__(NTHREADS, 2) void mfvi_kernel(
    const float* __restrict__ unary,
    const float* __restrict__ mask,
    const float* __restrict__ Tg,
    const float* __restrict__ tstart,
    const float* __restrict__ tend,
    float* __restrict__ out)
{
    extern __shared__ char dsm_raw[];
    char* smp = (char*)(((uintptr_t)dsm_raw + 1023) & ~(uintptr_t)1023);
    uint32_t* AhiU = (uint32_t*)(smp + OFF_AHI);
    uint32_t* AloU = (uint32_t*)(smp + OFF_ALO);
    uint4*    Bf   = (uint4*)   (smp + OFF_BF);
    float*    Dsm  = (float*)   (smp + OFF_D);
    float*    Usm  = (float*)   (smp + OFF_U);
    float*    Msk  = (float*)   (smp + OFF_MSK);
    float*    Tss  = (float*)   (smp + OFF_TS);
    float*    Tes  = (float*)   (smp + OFF_TE);

    const int n    = blockIdx.y;
    const int p0   = blockIdx.x * TILE;
    const int base = p0 - 3;
    const int tid  = threadIdx.x;

    // ---- prologue: zero A hi+lo frag regions (halo rows must stay 0) ----
    {
        float4 z = make_float4(0.f, 0.f, 0.f, 0.f);
        for (int i = tid; i < (int)(32768 / 16); i += NTHREADS)
            ((float4*)(smp + OFF_AHI))[i] = z;
    }
    // ---- B fragments, bf16 hi/lo, m16n8k16 col-major fragment order ----
    // B'[bn][k]: k<50 -> T[k][bn] ; 64<=k<114 -> T[bn][k-64] ; else 0
    for (int idx = tid; idx < 7 * 8 * 32; idx += NTHREADS) {
        int lane = idx & 31, rem = idx >> 5;
        int ks = rem & 7, nt = rem >> 3;
        int gI = lane >> 2, tI = lane & 3;
        int bn = nt * 8 + gI;
        int k0 = 16 * ks + 2 * tI;
        float v[4];
        #pragma unroll
        for (int h = 0; h < 4; h++) {
            int k = k0 + (h >> 1) * 8 + (h & 1);
            float val = 0.f;
            if (bn < L) {
                if (k < L)                        val = Tg[k * L + bn];
                else if (k >= 64 && k < 64 + L)   val = Tg[bn * L + (k - 64)];
            }
            v[h] = val;
        }
        uint4 o;
        o.x = bfpack(v[0], v[1]);
        o.y = bfpack(v[2], v[3]);
        o.z = bfpack(v[0] - bfhi(v[0]), v[1] - bfhi(v[1]));
        o.w = bfpack(v[2] - bfhi(v[2]), v[3] - bfhi(v[3]));
        Bf[idx] = o;
    }
    if (tid < RROWS) {
        int g = base + tid;
        Msk[tid] = (g >= 0 && g < S_LEN) ? mask[(size_t)n * S_LEN + g] : 0.f;
    }
    if (tid < 64) {
        Tss[tid] = (tid < L) ? tstart[tid] : 0.f;
        Tes[tid] = (tid < L) ? tend[tid]   : 0.f;
    }
    __syncthreads();
    for (int idx = tid; idx < RROWS * UST; idx += NTHREADS) {
        int rr = idx / UST, c = idx - rr * UST;
        int gg = base + rr;
        float v = 0.f;
        if (c < L && gg >= 0 && gg < S_LEN)
            v = unary[((size_t)n * S_LEN + gg) * L + c] * Msk[rr];
        Usm[idx] = v;
    }
    __syncthreads();

    #pragma unroll 1
    for (int it = 0; it <= 3; it++) {
        // ==== build: 8 threads/row, thread = 8-label strip ====
        {
            const int r     = tid >> 3;
            const int sub   = tid & 7;
            const int cbase = 8 * sub;
            const int cnt   = (sub < 6) ? 8 : (sub == 6 ? 2 : 0);
            const int g     = base + r;
            const bool act  = (g >= 0) && (g < S_LEN) && (r >= it) && (r < RROWS - it);

            float q[8];
            if (it == 0) {
                float4 u0 = *(const float4*)&Usm[r * UST + cbase];
                float4 u1 = *(const float4*)&Usm[r * UST + cbase + 4];
                q[0]=u0.x; q[1]=u0.y; q[2]=u0.z; q[3]=u0.w;
                q[4]=u1.x; q[5]=u1.y; q[6]=u1.z; q[7]=u1.w;
            } else {
                const float  m   = Msk[r];
                const float* bnd = (g == 0) ? Tss : Tes;  // pos0: tstart; >=1: tend
                float4 u0 = *(const float4*)&Usm[r * UST + cbase];
                float4 u1 = *(const float4*)&Usm[r * UST + cbase + 4];
                float4 d0 = *(const float4*)&Dsm[r * DST + cbase];
                float4 d1 = *(const float4*)&Dsm[r * DST + cbase + 4];
                float4 b0 = *(const float4*)&bnd[cbase];
                float4 b1 = *(const float4*)&bnd[cbase + 4];
                q[0]=(u0.x+d0.x+b0.x)*m; q[1]=(u0.y+d0.y+b0.y)*m;
                q[2]=(u0.z+d0.z+b0.z)*m; q[3]=(u0.w+d0.w+b0.w)*m;
                q[4]=(u1.x+d1.x+b1.x)*m; q[5]=(u1.y+d1.y+b1.y)*m;
                q[6]=(u1.z+d1.z+b1.z)*m; q[7]=(u1.w+d1.w+b1.w)*m;
            }
            if (it == 3) {
                if (act) {
                    float* st = (float*)(smp + OFF_AHI);   // frag region as staging
                    #pragma unroll
                    for (int i = 0; i < 8; i++)
                        if (i < cnt) st[(r - 3) * 50 + cbase + i] = q[i];
                }
            } else {
                float mx = -3.4e38f;
                #pragma unroll
                for (int i = 0; i < 8; i++) if (i < cnt) mx = fmaxf(mx, q[i]);
                #pragma unroll
                for (int o = 1; o < 8; o <<= 1)
                    mx = fmaxf(mx, __shfl_xor_sync(0xffffffffu, mx, o));
                float s = 0.f;
                #pragma unroll
                for (int i = 0; i < 8; i++)
                    if (i < cnt) { q[i] = __expf(q[i] - mx); s += q[i]; }
                #pragma unroll
                for (int o = 1; o < 8; o <<= 1)
                    s += __shfl_xor_sync(0xffffffffu, s, o);
                float inv = __fdividef(1.f, s);
                if (act) {
                    const int np = cnt >> 1;
                    // left-copy -> A row r+1 words 4sub+pi ; right-copy -> r-1, +32
                    #pragma unroll
                    for (int pi = 0; pi < 4; pi++) {
                        if (pi < np) {
                            float pa = q[2 * pi] * inv;
                            float pz = q[2 * pi + 1] * inv;
                            uint32_t ph = bfpack(pa, pz);
                            uint32_t pl = bfpack(pa - bfhi(pa), pz - bfhi(pz));
                            if (r + 1 < RROWS) {
                                int ix = fragidx(r + 1, 4 * sub + pi);
                                AhiU[ix] = ph;  AloU[ix] = pl;
                            }
                            if (r - 1 >= 0) {
                                int ix = fragidx(r - 1, 32 + 4 * sub + pi);
                                AhiU[ix] = ph;  AloU[ix] = pl;
                            }
                        }
                    }
                }
            }
        }
        __syncthreads();
        if (it == 3) break;

        // ==== MMA: 16 warps = 4 row-blocks x 4 col-groups, bf16 3-split ====
        {
            const int w   = tid >> 5;
            const int l   = tid & 31;
            const int gID = l >> 2;
            const int tID = l & 3;
            const int rb  = w >> 2;
            const int R0  = 16 * rb;
            const int cg  = w & 3;
            const int nt0 = 2 * cg;
            const int ntc = (cg < 3) ? 2 : 1;

            float acc[2][4];
            #pragma unroll
            for (int j = 0; j < 2; j++)
                #pragma unroll
                for (int k = 0; k < 4; k++) acc[j][k] = 0.f;

            const uint4* Ah4 = (const uint4*)(smp + OFF_AHI);
            const uint4* Al4 = (const uint4*)(smp + OFF_ALO);
            #pragma unroll
            for (int ks = 0; ks < 8; ks++) {
                uint4 ah = Ah4[(rb * 8 + ks) * 32 + l];
                uint4 al = Al4[(rb * 8 + ks) * 32 + l];
                const uint4* bp = Bf + (nt0 * 8 + ks) * 32 + l;
                #pragma unroll
                for (int j = 0; j < 2; j++) {
                    if (j < ntc) {                        // warp-uniform guard
                        uint4 b = bp[j * 8 * 32];
                        mma16(acc[j], ah.x, ah.y, ah.z, ah.w, b.x, b.y);
                        mma16(acc[j], al.x, al.y, al.z, al.w, b.x, b.y);
                        mma16(acc[j], ah.x, ah.y, ah.z, ah.w, b.z, b.w);
                    }
                }
            }
            #pragma unroll
            for (int j = 0; j < 2; j++) {
                if (j < ntc) {
                    int c0 = (nt0 + j) * 8 + 2 * tID;
                    *(float2*)&Dsm[(R0 + gID) * DST + c0] =
                        make_float2(acc[j][0], acc[j][1]);
                    *(float2*)&Dsm[(R0 + gID + 8) * DST + c0] =
                        make_float2(acc[j][2], acc[j][3]);
                }
            }
        }
        __syncthreads();
    }

    // ---- epilogue: coalesced staging -> global ----
    {
        int rows = min(TILE, S_LEN - p0);
        int nvec = rows * L / 4;
        const float4* s4 = (const float4*)(smp + OFF_AHI);
        float4* o4 = (float4*)(out + ((size_t)n * S_LEN + p0) * L);
        for (int i = tid; i < nvec; i += NTHREADS) o4[i] = s4[i];
        int rem = rows * L - nvec * 4;
        if (tid < rem) {
            const float* sf = (const float*)(smp + OFF_AHI);
            out[((size_t)n * S_LEN + p0) * L + nvec * 4 + tid] = sf[nvec * 4 + tid];
        }
    }
}

extern "C" void kernel_launch(void* const* d_in, const int* in_sizes, int n_in,
                              void* d_out, int out_size)
{
    const float* unary = (const float*)d_in[0];
    const float* mask  = (const float*)d_in[1];
    const float* T     = (const float*)d_in[2];
    const float* ts    = (const float*)d_in[3];
    const float* te    = (const float*)d_in[4];
    (void)n_in; (void)out_size;

    cudaFuncSetAttribute(mfvi_kernel,
                         cudaFuncAttributeMaxDynamicSharedMemorySize, SMEM_BYTES);

    int NS = in_sizes[1];
    int N  = NS / S_LEN;
    dim3 grid(NTILES, N);
    mfvi_kernel<<<grid, NTHREADS, SMEM_BYTES>>>(unary, mask, T, ts, te, (float*)d_out);
}

// round 13
// speedup vs baseline: 1.8026x; 1.6095x over previous
#include <cuda_runtime.h>
#include <cuda_fp16.h>
#include <cstdint>

#define S_LEN    2048
#define L        50
#define TILE     122
#define RROWS    128
#define NTHREADS 256
#define NTILES   ((S_LEN + TILE - 1) / TILE)   // 17

#define UST 56    // floats per U row (16B-aligned rows)

// smem byte offsets from 1024-aligned base
#define OFF_AHI 0u          // A hi frags: 8 rb x 8 ks x 32 lanes x uint4 = 32768
#define OFF_ALO 32768u
#define OFF_BH  65536u      // B hi frags: 7 nt x 8 ks x 32 lanes x uint2 = 14336
#define OFF_U   79872u      // 128 x 56 x 4 = 28672
#define OFF_MSK 108544u
#define OFF_TS  109056u
#define OFF_TE  109312u
#define SMEM_BYTES (109568 + 1024)

__device__ __forceinline__ uint32_t hpack(float e0, float e1) {
    uint32_t r;
    asm("cvt.rn.f16x2.f32 %0, %1, %2;" : "=r"(r) : "f"(e1), "f"(e0));
    return r;   // lower half = e0, upper = e1
}
__device__ __forceinline__ float hhi(float v) {
    return __half2float(__float2half_rn(v));
}
__device__ __forceinline__ void mma16(float* d, uint32_t a0, uint32_t a1,
                                      uint32_t a2, uint32_t a3,
                                      uint32_t b0, uint32_t b1) {
    asm volatile(
        "mma.sync.aligned.m16n8k16.row.col.f32.f16.f16.f32 "
        "{%0,%1,%2,%3}, {%4,%5,%6,%7}, {%8,%9}, {%0,%1,%2,%3};"
        : "+f"(d[0]), "+f"(d[1]), "+f"(d[2]), "+f"(d[3])
        : "r"(a0), "r"(a1), "r"(a2), "r"(a3), "r"(b0), "r"(b1));
}

// word index (uint32) of A-fragment word (row, w) — validated layout from R12
__device__ __forceinline__ int fragidx(int row, int w) {
    int rb = row >> 4, rr = row & 15;
    int ks = w >> 3, win = w & 7, tI = win & 3;
    int c = ((win >= 4) ? 2 : 0) + ((rr >= 8) ? 1 : 0);
    return (((rb * 8 + ks) * 32) + (rr & 7) * 4 + tI) * 4 + c;
}

__global__ __launch_bounds__(NTHREADS, 2) void mfvi_kernel(
    const float* __restrict__ unary,
    const float* __restrict__ mask,
    const float* __restrict__ Tg,
    const float* __restrict__ tstart,
    const float* __restrict__ tend,
    float* __restrict__ out)
{
    extern __shared__ char dsm_raw[];
    char* smp = (char*)(((uintptr_t)dsm_raw + 1023) & ~(uintptr_t)1023);
    uint32_t* AhiU = (uint32_t*)(smp + OFF_AHI);
    uint32_t* AloU = (uint32_t*)(smp + OFF_ALO);
    uint2*    BH   = (uint2*)   (smp + OFF_BH);
    float*    Usm  = (float*)   (smp + OFF_U);
    float*    Msk  = (float*)   (smp + OFF_MSK);
    float*    Tss  = (float*)   (smp + OFF_TS);
    float*    Tes  = (float*)   (smp + OFF_TE);

    const int n    = blockIdx.y;
    const int p0   = blockIdx.x * TILE;
    const int base = p0 - 3;
    const int tid  = threadIdx.x;
    const int w    = tid >> 5;            // warp = row-block 0..7
    const int l    = tid & 31;
    const int gID  = l >> 2;
    const int tID  = l & 3;
    const int r    = 16 * w + gID;        // this lane's first row
    const int r8   = r + 8;               // second row
    const int ga   = base + r;
    const int gb   = base + r8;

    // ---- prologue: zero A hi+lo frag regions (never-written words must be 0) ----
    {
        float4 z = make_float4(0.f, 0.f, 0.f, 0.f);
        for (int i = tid; i < (int)(65536 / 16); i += NTHREADS)
            ((float4*)(smp + OFF_AHI))[i] = z;
    }
    // ---- B hi fragments (fp16), m16n8k16 col-major fragment order ----
    // B'[bn][k]: k<50 -> T[k][bn] ; 64<=k<114 -> T[bn][k-64] ; else 0
    for (int idx = tid; idx < 7 * 8 * 32; idx += NTHREADS) {
        int lane = idx & 31, rem = idx >> 5;
        int ks = rem & 7, nt = rem >> 3;
        int gI = lane >> 2, tI = lane & 3;
        int bn = nt * 8 + gI;
        int k0 = 16 * ks + 2 * tI;
        float v[4];
        #pragma unroll
        for (int h = 0; h < 4; h++) {
            int k = k0 + (h >> 1) * 8 + (h & 1);
            float val = 0.f;
            if (bn < L) {
                if (k < L)                        val = Tg[k * L + bn];
                else if (k >= 64 && k < 64 + L)   val = Tg[bn * L + (k - 64)];
            }
            v[h] = val;
        }
        BH[idx] = make_uint2(hpack(v[0], v[1]), hpack(v[2], v[3]));
    }
    if (tid < RROWS) {
        int g = base + tid;
        Msk[tid] = (g >= 0 && g < S_LEN) ? mask[(size_t)n * S_LEN + g] : 0.f;
    }
    if (tid < 64) {
        Tss[tid] = (tid < L) ? tstart[tid] : 0.f;
        Tes[tid] = (tid < L) ? tend[tid]   : 0.f;
    }
    __syncthreads();
    for (int idx = tid; idx < RROWS * UST; idx += NTHREADS) {
        int rr = idx / UST, c = idx - rr * UST;
        int gg = base + rr;
        float v = 0.f;
        if (c < L && gg >= 0 && gg < S_LEN)
            v = unary[((size_t)n * S_LEN + gg) * L + c] * Msk[rr];
        Usm[idx] = v;
    }
    __syncthreads();

    float acc[7][4];   // [nt]: {row r c0, row r c1, row r8 c0, row r8 c1}

    #pragma unroll 1
    for (int it = 0; it <= 3; it++) {
        const bool actA = (ga >= 0) && (ga < S_LEN) && (r  >= it) && (r  < RROWS - it);
        const bool actB = (gb >= 0) && (gb < S_LEN) && (r8 >= it) && (r8 < RROWS - it);

        // ==== combine: acc = (u*m + D + bnd) * m   (acc holds D from last MMA) ====
        {
            const float ma = Msk[r], mb = Msk[r8];
            #pragma unroll
            for (int nt = 0; nt < 7; nt++) {
                const int c0 = 8 * nt + 2 * tID;
                if (c0 < L) {
                    float2 ua = *(const float2*)&Usm[r  * UST + c0];
                    float2 ub = *(const float2*)&Usm[r8 * UST + c0];
                    if (it == 0) {
                        acc[nt][0] = ua.x; acc[nt][1] = ua.y;
                        acc[nt][2] = ub.x; acc[nt][3] = ub.y;
                    } else {
                        float2 ba = (ga == 0) ? *(const float2*)&Tss[c0]
                                              : *(const float2*)&Tes[c0];
                        float2 bb = *(const float2*)&Tes[c0];   // gb==0 impossible (r8>=8)
                        acc[nt][0] = (ua.x + acc[nt][0] + ba.x) * ma;
                        acc[nt][1] = (ua.y + acc[nt][1] + ba.y) * ma;
                        acc[nt][2] = (ub.x + acc[nt][2] + bb.x) * mb;
                        acc[nt][3] = (ub.y + acc[nt][3] + bb.y) * mb;
                    }
                }
            }
        }

        if (it == 3) {
            // ==== final write to global (no softmax) ====
            #pragma unroll
            for (int nt = 0; nt < 7; nt++) {
                const int c0 = 8 * nt + 2 * tID;
                if (c0 < L) {
                    if (actA)
                        *(float2*)&out[((size_t)n * S_LEN + ga) * L + c0] =
                            make_float2(acc[nt][0], acc[nt][1]);
                    if (actB)
                        *(float2*)&out[((size_t)n * S_LEN + gb) * L + c0] =
                            make_float2(acc[nt][2], acc[nt][3]);
                }
            }
            break;
        }

        // ==== softmax per row via quad shuffles ====
        {
            float mxa = -3.4e38f, mxb = -3.4e38f;
            #pragma unroll
            for (int nt = 0; nt < 7; nt++) {
                const int c0 = 8 * nt + 2 * tID;
                if (c0 < L) {
                    mxa = fmaxf(mxa, fmaxf(acc[nt][0], acc[nt][1]));
                    mxb = fmaxf(mxb, fmaxf(acc[nt][2], acc[nt][3]));
                }
            }
            mxa = fmaxf(mxa, __shfl_xor_sync(0xffffffffu, mxa, 1));
            mxb = fmaxf(mxb, __shfl_xor_sync(0xffffffffu, mxb, 1));
            mxa = fmaxf(mxa, __shfl_xor_sync(0xffffffffu, mxa, 2));
            mxb = fmaxf(mxb, __shfl_xor_sync(0xffffffffu, mxb, 2));
            float sa = 0.f, sb = 0.f;
            #pragma unroll
            for (int nt = 0; nt < 7; nt++) {
                const int c0 = 8 * nt + 2 * tID;
                if (c0 < L) {
                    acc[nt][0] = __expf(acc[nt][0] - mxa);
                    acc[nt][1] = __expf(acc[nt][1] - mxa);
                    acc[nt][2] = __expf(acc[nt][2] - mxb);
                    acc[nt][3] = __expf(acc[nt][3] - mxb);
                    sa += acc[nt][0] + acc[nt][1];
                    sb += acc[nt][2] + acc[nt][3];
                }
            }
            sa += __shfl_xor_sync(0xffffffffu, sa, 1);
            sb += __shfl_xor_sync(0xffffffffu, sb, 1);
            sa += __shfl_xor_sync(0xffffffffu, sa, 2);
            sb += __shfl_xor_sync(0xffffffffu, sb, 2);
            float ia = __fdividef(1.f, sa);
            float ib = __fdividef(1.f, sb);

            // ==== write A-fragments (hi/lo fp16) for next MMA ====
            #pragma unroll
            for (int nt = 0; nt < 7; nt++) {
                const int c0 = 8 * nt + 2 * tID;
                if (c0 < L) {
                    const int wd = 4 * nt + tID;
                    if (actA) {
                        float p0v = acc[nt][0] * ia, p1v = acc[nt][1] * ia;
                        uint32_t ph = hpack(p0v, p1v);
                        uint32_t pl = hpack(p0v - hhi(p0v), p1v - hhi(p1v));
                        if (r + 1 < RROWS) {                // left copy
                            int ix = fragidx(r + 1, wd);
                            AhiU[ix] = ph;  AloU[ix] = pl;
                        }
                        if (r - 1 >= 0) {                   // right copy
                            int ix = fragidx(r - 1, 32 + wd);
                            AhiU[ix] = ph;  AloU[ix] = pl;
                        }
                    }
                    if (actB) {
                        float p0v = acc[nt][2] * ib, p1v = acc[nt][3] * ib;
                        uint32_t ph = hpack(p0v, p1v);
                        uint32_t pl = hpack(p0v - hhi(p0v), p1v - hhi(p1v));
                        if (r8 + 1 < RROWS) {
                            int ix = fragidx(r8 + 1, wd);
                            AhiU[ix] = ph;  AloU[ix] = pl;
                        }
                        {                                   // r8-1 >= 7 always
                            int ix = fragidx(r8 - 1, 32 + wd);
                            AhiU[ix] = ph;  AloU[ix] = pl;
                        }
                    }
                }
            }
        }
        __syncthreads();

        // ==== MMA: warp w = rows [16w,16w+16), all 7 col-groups, fp16 2-split ====
        {
            #pragma unroll
            for (int nt = 0; nt < 7; nt++)
                #pragma unroll
                for (int j = 0; j < 4; j++) acc[nt][j] = 0.f;

            const uint4* Ah4 = (const uint4*)(smp + OFF_AHI);
            const uint4* Al4 = (const uint4*)(smp + OFF_ALO);
            #pragma unroll
            for (int ks = 0; ks < 8; ks++) {
                uint4 ah = Ah4[(w * 8 + ks) * 32 + l];
                uint4 al = Al4[(w * 8 + ks) * 32 + l];
                #pragma unroll
                for (int nt = 0; nt < 7; nt++) {
                    uint2 b = BH[(nt * 8 + ks) * 32 + l];
                    mma16(acc[nt], ah.x, ah.y, ah.z, ah.w, b.x, b.y);
                    mma16(acc[nt], al.x, al.y, al.z, al.w, b.x, b.y);
                }
            }
        }
        __syncthreads();
    }
}

extern "C" void kernel_launch(void* const* d_in, const int* in_sizes, int n_in,
                              void* d_out, int out_size)
{
    const float* unary = (const float*)d_in[0];
    const float* mask  = (const float*)d_in[1];
    const float* T     = (const float*)d_in[2];
    const float* ts    = (const float*)d_in[3];
    const float* te    = (const float*)d_in[4];
    (void)n_in; (void)out_size;

    cudaFuncSetAttribute(mfvi_kernel,
                         cudaFuncAttributeMaxDynamicSharedMemorySize, SMEM_BYTES);

    int NS = in_sizes[1];
    int N  = NS / S_LEN;
    dim3 grid(NTILES, N);
    mfvi_kernel<<<grid, NTHREADS, SMEM_BYTES>>>(unary, mask, T, ts, te, (float*)d_out);
}

// round 14
// speedup vs baseline: 2.4592x; 1.3643x over previous
#include <cuda_runtime.h>
#include <cuda_fp16.h>
#include <cstdint>

#define S_LEN    2048
#define L        50
#define TILE     122
#define RROWS    128
#define NTHREADS 256
#define NTILES   ((S_LEN + TILE - 1) / TILE)   // 17

// K packing: left msg k 0..49, right msg k 56..105, K=112 (7 ks of 16)
#define NKS 7

// smem byte offsets from 1024-aligned base
#define OFF_AHI 0u          // A hi frags: 8 rb x 7 ks x 32 lanes x uint4 = 28672
#define OFF_ALO 28672u
#define OFF_BH  57344u      // B hi frags: 7 nt x 7 ks x 32 lanes x uint2 = 12544
#define OFF_MSK 69888u
#define OFF_TS  70400u
#define OFF_TE  70656u
#define SMEM_BYTES (70912 + 1024)

__device__ __forceinline__ uint32_t hpack(float e0, float e1) {
    uint32_t r;
    asm("cvt.rn.f16x2.f32 %0, %1, %2;" : "=r"(r) : "f"(e1), "f"(e0));
    return r;   // lower half = e0, upper = e1
}
__device__ __forceinline__ float hhi(float v) {
    return __half2float(__float2half_rn(v));
}
__device__ __forceinline__ void mma16(float* d, uint32_t a0, uint32_t a1,
                                      uint32_t a2, uint32_t a3,
                                      uint32_t b0, uint32_t b1) {
    asm volatile(
        "mma.sync.aligned.m16n8k16.row.col.f32.f16.f16.f32 "
        "{%0,%1,%2,%3}, {%4,%5,%6,%7}, {%8,%9}, {%0,%1,%2,%3};"
        : "+f"(d[0]), "+f"(d[1]), "+f"(d[2]), "+f"(d[3])
        : "r"(a0), "r"(a1), "r"(a2), "r"(a3), "r"(b0), "r"(b1));
}

// word index (uint32) of A-fragment word (row, w); 7 ks per row-block
__device__ __forceinline__ int fragidx(int row, int w) {
    int rb = row >> 4, rr = row & 15;
    int ks = w >> 3, win = w & 7, tI = win & 3;
    int c = ((win >= 4) ? 2 : 0) + ((rr >= 8) ? 1 : 0);
    return (((rb * NKS + ks) * 32) + (rr & 7) * 4 + tI) * 4 + c;
}

__global__ __launch_bounds__(NTHREADS, 3) void mfvi_kernel(
    const float* __restrict__ unary,
    const float* __restrict__ mask,
    const float* __restrict__ Tg,
    const float* __restrict__ tstart,
    const float* __restrict__ tend,
    float* __restrict__ out)
{
    extern __shared__ char dsm_raw[];
    char* smp = (char*)(((uintptr_t)dsm_raw + 1023) & ~(uintptr_t)1023);
    uint32_t* AhiU = (uint32_t*)(smp + OFF_AHI);
    uint32_t* AloU = (uint32_t*)(smp + OFF_ALO);
    uint2*    BH   = (uint2*)   (smp + OFF_BH);
    float*    Msk  = (float*)   (smp + OFF_MSK);
    float*    Tss  = (float*)   (smp + OFF_TS);
    float*    Tes  = (float*)   (smp + OFF_TE);

    const int n    = blockIdx.y;
    const int p0   = blockIdx.x * TILE;
    const int base = p0 - 3;
    const int tid  = threadIdx.x;
    const int w    = tid >> 5;            // warp = row-block 0..7
    const int l    = tid & 31;
    const int gID  = l >> 2;
    const int tID  = l & 3;
    const int r    = 16 * w + gID;        // this lane's first row
    const int r8   = r + 8;               // second row
    const int ga   = base + r;
    const int gb   = base + r8;
    const bool vA  = (ga >= 0) && (ga < S_LEN);
    const bool vB  = (gb >= 0) && (gb < S_LEN);
    const float* uA = unary + ((size_t)n * S_LEN + (vA ? ga : 0)) * L;
    const float* uB = unary + ((size_t)n * S_LEN + (vB ? gb : 0)) * L;

    // ---- prologue: zero A hi+lo frag regions (never-written words must be 0) ----
    {
        float4 z = make_float4(0.f, 0.f, 0.f, 0.f);
        for (int i = tid; i < (int)(2 * 28672 / 16); i += NTHREADS)
            ((float4*)(smp + OFF_AHI))[i] = z;
    }
    // ---- B hi fragments (fp16), m16n8k16 col-major fragment order ----
    // B'[bn][k]: k<50 -> T[k][bn] ; 56<=k<106 -> T[bn][k-56] ; else 0
    for (int idx = tid; idx < 7 * NKS * 32; idx += NTHREADS) {
        int lane = idx & 31, rem = idx >> 5;
        int ks = rem % NKS, nt = rem / NKS;
        int gI = lane >> 2, tI = lane & 3;
        int bn = nt * 8 + gI;
        int k0 = 16 * ks + 2 * tI;
        float v[4];
        #pragma unroll
        for (int h = 0; h < 4; h++) {
            int k = k0 + (h >> 1) * 8 + (h & 1);
            float val = 0.f;
            if (bn < L) {
                if (k < L)                        val = Tg[k * L + bn];
                else if (k >= 56 && k < 56 + L)   val = Tg[bn * L + (k - 56)];
            }
            v[h] = val;
        }
        BH[(nt * NKS + ks) * 32 + lane] = make_uint2(hpack(v[0], v[1]), hpack(v[2], v[3]));
    }
    if (tid < RROWS) {
        int g = base + tid;
        Msk[tid] = (g >= 0 && g < S_LEN) ? mask[(size_t)n * S_LEN + g] : 0.f;
    }
    if (tid < 64) {
        Tss[tid] = (tid < L) ? tstart[tid] : 0.f;
        Tes[tid] = (tid < L) ? tend[tid]   : 0.f;
    }
    __syncthreads();

    float acc[7][4];   // [nt]: {row r c0, row r c1, row r8 c0, row r8 c1}

    #pragma unroll 1
    for (int it = 0; it <= 3; it++) {
        const bool actA = vA && (r  >= it) && (r  < RROWS - it);
        const bool actB = vB && (r8 >= it) && (r8 < RROWS - it);

        // ==== combine: acc = (u*m + D + bnd) * m   (acc holds D from last MMA) ====
        {
            const float ma = Msk[r], mb = Msk[r8];
            #pragma unroll
            for (int nt = 0; nt < 7; nt++) {
                const int c0 = 8 * nt + 2 * tID;
                if (c0 < L) {
                    float2 ua = vA ? *(const float2*)&uA[c0] : make_float2(0.f, 0.f);
                    float2 ub = vB ? *(const float2*)&uB[c0] : make_float2(0.f, 0.f);
                    if (it == 0) {
                        acc[nt][0] = ua.x * ma; acc[nt][1] = ua.y * ma;
                        acc[nt][2] = ub.x * mb; acc[nt][3] = ub.y * mb;
                    } else {
                        float2 ba = (ga == 0) ? *(const float2*)&Tss[c0]
                                              : *(const float2*)&Tes[c0];
                        float2 bb = *(const float2*)&Tes[c0];   // gb==0 impossible (r8>=8)
                        acc[nt][0] = (ua.x * ma + acc[nt][0] + ba.x) * ma;
                        acc[nt][1] = (ua.y * ma + acc[nt][1] + ba.y) * ma;
                        acc[nt][2] = (ub.x * mb + acc[nt][2] + bb.x) * mb;
                        acc[nt][3] = (ub.y * mb + acc[nt][3] + bb.y) * mb;
                    }
                }
            }
        }

        if (it == 3) {
            // ==== final write to global ====
            #pragma unroll
            for (int nt = 0; nt < 7; nt++) {
                const int c0 = 8 * nt + 2 * tID;
                if (c0 < L) {
                    if (actA)
                        *(float2*)&out[((size_t)n * S_LEN + ga) * L + c0] =
                            make_float2(acc[nt][0], acc[nt][1]);
                    if (actB)
                        *(float2*)&out[((size_t)n * S_LEN + gb) * L + c0] =
                            make_float2(acc[nt][2], acc[nt][3]);
                }
            }
            break;
        }

        // ==== softmax per row via quad shuffles ====
        {
            float mxa = -3.4e38f, mxb = -3.4e38f;
            #pragma unroll
            for (int nt = 0; nt < 7; nt++) {
                const int c0 = 8 * nt + 2 * tID;
                if (c0 < L) {
                    mxa = fmaxf(mxa, fmaxf(acc[nt][0], acc[nt][1]));
                    mxb = fmaxf(mxb, fmaxf(acc[nt][2], acc[nt][3]));
                }
            }
            mxa = fmaxf(mxa, __shfl_xor_sync(0xffffffffu, mxa, 1));
            mxb = fmaxf(mxb, __shfl_xor_sync(0xffffffffu, mxb, 1));
            mxa = fmaxf(mxa, __shfl_xor_sync(0xffffffffu, mxa, 2));
            mxb = fmaxf(mxb, __shfl_xor_sync(0xffffffffu, mxb, 2));
            float sa = 0.f, sb = 0.f;
            #pragma unroll
            for (int nt = 0; nt < 7; nt++) {
                const int c0 = 8 * nt + 2 * tID;
                if (c0 < L) {
                    acc[nt][0] = __expf(acc[nt][0] - mxa);
                    acc[nt][1] = __expf(acc[nt][1] - mxa);
                    acc[nt][2] = __expf(acc[nt][2] - mxb);
                    acc[nt][3] = __expf(acc[nt][3] - mxb);
                    sa += acc[nt][0] + acc[nt][1];
                    sb += acc[nt][2] + acc[nt][3];
                }
            }
            sa += __shfl_xor_sync(0xffffffffu, sa, 1);
            sb += __shfl_xor_sync(0xffffffffu, sb, 1);
            sa += __shfl_xor_sync(0xffffffffu, sa, 2);
            sb += __shfl_xor_sync(0xffffffffu, sb, 2);
            float ia = __fdividef(1.f, sa);
            float ib = __fdividef(1.f, sb);

            // ==== write A-fragments (hi/lo fp16) for next MMA ====
            // left copy -> word 4nt+tID of row r+1 ; right copy -> word 28+4nt+tID of r-1
            #pragma unroll
            for (int nt = 0; nt < 7; nt++) {
                const int c0 = 8 * nt + 2 * tID;
                if (c0 < L) {
                    const int wd = 4 * nt + tID;
                    if (actA) {
                        float p0v = acc[nt][0] * ia, p1v = acc[nt][1] * ia;
                        uint32_t ph = hpack(p0v, p1v);
                        uint32_t pl = hpack(p0v - hhi(p0v), p1v - hhi(p1v));
                        if (r + 1 < RROWS) {
                            int ix = fragidx(r + 1, wd);
                            AhiU[ix] = ph;  AloU[ix] = pl;
                        }
                        if (r - 1 >= 0) {
                            int ix = fragidx(r - 1, 28 + wd);
                            AhiU[ix] = ph;  AloU[ix] = pl;
                        }
                    }
                    if (actB) {
                        float p0v = acc[nt][2] * ib, p1v = acc[nt][3] * ib;
                        uint32_t ph = hpack(p0v, p1v);
                        uint32_t pl = hpack(p0v - hhi(p0v), p1v - hhi(p1v));
                        if (r8 + 1 < RROWS) {
                            int ix = fragidx(r8 + 1, wd);
                            AhiU[ix] = ph;  AloU[ix] = pl;
                        }
                        {                                   // r8-1 >= 7 always
                            int ix = fragidx(r8 - 1, 28 + wd);
                            AhiU[ix] = ph;  AloU[ix] = pl;
                        }
                    }
                }
            }
        }
        __syncthreads();

        // ==== MMA: warp w = rows [16w,16w+16), all 7 col-groups, fp16 2-split ====
        {
            #pragma unroll
            for (int nt = 0; nt < 7; nt++)
                #pragma unroll
                for (int j = 0; j < 4; j++) acc[nt][j] = 0.f;

            const uint4* Ah4 = (const uint4*)(smp + OFF_AHI);
            const uint4* Al4 = (const uint4*)(smp + OFF_ALO);
            #pragma unroll
            for (int ks = 0; ks < NKS; ks++) {
                uint4 ah = Ah4[(w * NKS + ks) * 32 + l];
                uint4 al = Al4[(w * NKS + ks) * 32 + l];
                #pragma unroll
                for (int nt = 0; nt < 7; nt++) {
                    uint2 b = BH[(nt * NKS + ks) * 32 + l];
                    mma16(acc[nt], ah.x, ah.y, ah.z, ah.w, b.x, b.y);
                    mma16(acc[nt], al.x, al.y, al.z, al.w, b.x, b.y);
                }
            }
        }
        __syncthreads();
    }
}

extern "C" void kernel_launch(void* const* d_in, const int* in_sizes, int n_in,
                              void* d_out, int out_size)
{
    const float* unary = (const float*)d_in[0];
    const float* mask  = (const float*)d_in[1];
    const float* T     = (const float*)d_in[2];
    const float* ts    = (const float*)d_in[3];
    const float* te    = (const float*)d_in[4];
    (void)n_in; (void)out_size;

    cudaFuncSetAttribute(mfvi_kernel,
                         cudaFuncAttributeMaxDynamicSharedMemorySize, SMEM_BYTES);

    int NS = in_sizes[1];
    int N  = NS / S_LEN;
    dim3 grid(NTILES, N);
    mfvi_kernel<<<grid, NTHREADS, SMEM_BYTES>>>(unary, mask, T, ts, te, (float*)d_out);
}